// round 5
// baseline (speedup 1.0000x reference)
#include <cuda_runtime.h>
#include <cuda_bf16.h>
#include <cstdint>

// ---------------------------------------------------------------------------
// Problem constants
// ---------------------------------------------------------------------------
#define NPF 20000
#define NGW 100000
#define NSW 30000
#define D   128

#define EPG 1600000
#define EGP 640000
#define EPS 480000
#define ESP 320000
#define ETOT (EPG + EGP + EPS + ESP)

#define NTOT (NGW + NPF + NSW + NPF)

// ---------------------------------------------------------------------------
// Device scratch (no allocations allowed -> __device__ globals)
// ---------------------------------------------------------------------------
__device__ float g_mean_gw[(size_t)NGW * D];
__device__ float g_mean_sw[(size_t)NSW * D];
__device__ float g_mean_gp[(size_t)NPF * D];
__device__ float g_mean_sp[(size_t)NPF * D];
__device__ int   g_cnt[NTOT];
__device__ int   g_rowptr[NTOT];
__device__ int   g_cursor[NTOT];
__device__ int   g_perm[ETOT];
__device__ int   g_partials[4 * 128];
__device__ float g_wr_comb[D * D];

// ---------------------------------------------------------------------------
// small utility kernels
// ---------------------------------------------------------------------------
__global__ void zero_int_kernel(int* __restrict__ p, int n4) {
    int i = blockIdx.x * blockDim.x + threadIdx.x;
    if (i < n4) reinterpret_cast<int4*>(p)[i] = make_int4(0, 0, 0, 0);
}

__global__ void addw_kernel(const float* __restrict__ a, const float* __restrict__ b,
                            float* __restrict__ o) {
    int i = blockIdx.x * blockDim.x + threadIdx.x;
    if (i < D * D) o[i] = a[i] + b[i];
}

// ---------------------------------------------------------------------------
// Fused CSR build: one histogram over all 4 relations
// ---------------------------------------------------------------------------
__global__ void hist_f(const int* __restrict__ pgd, const int* __restrict__ gpd,
                       const int* __restrict__ psd, const int* __restrict__ spd,
                       int* __restrict__ cnt) {
    int e = blockIdx.x * blockDim.x + threadIdx.x;
    if (e < EPG)                        atomicAdd(&cnt[pgd[e]], 1);
    else if (e < EPG + EGP)             atomicAdd(&cnt[NGW + gpd[e - EPG]], 1);
    else if (e < EPG + EGP + EPS)       atomicAdd(&cnt[NGW + NPF + psd[e - EPG - EGP]], 1);
    else if (e < ETOT)                  atomicAdd(&cnt[NGW + NPF + NSW + spd[e - EPG - EGP - EPS]], 1);
}

// fused per-relation scan: grid.y = relation, 1024 elements per block
__global__ void scan_reduce_f(const int* __restrict__ cnt, int* __restrict__ partials) {
    const int nbs[4]  = {98, 20, 30, 20};
    const int offs[4] = {0, NGW, NGW + NPF, NGW + NPF + NSW};
    const int ns[4]   = {NGW, NPF, NSW, NPF};
    int r = blockIdx.y;
    if ((int)blockIdx.x >= nbs[r]) return;
    const int* c = cnt + offs[r];
    int n = ns[r];
    __shared__ int s[256];
    int t = threadIdx.x;
    int base = blockIdx.x * 1024 + t * 4;
    int sum = 0;
#pragma unroll
    for (int j = 0; j < 4; j++) {
        int idx = base + j;
        if (idx < n) sum += c[idx];
    }
    s[t] = sum;
    __syncthreads();
    for (int off = 128; off > 0; off >>= 1) {
        if (t < off) s[t] += s[t + off];
        __syncthreads();
    }
    if (t == 0) partials[r * 128 + blockIdx.x] = s[0];
}

__global__ void scan_partials_f(int* __restrict__ partials) {
    const int nbs[4] = {98, 20, 30, 20};
    int r = threadIdx.x;
    if (r >= 4) return;
    int* p = partials + r * 128;
    int run = 0;
    for (int i = 0; i < nbs[r]; i++) {
        int v = p[i];
        p[i] = run;
        run += v;
    }
}

__global__ void scan_write_f(const int* __restrict__ cnt,
                             const int* __restrict__ partials,
                             int* __restrict__ rowptr,
                             int* __restrict__ cursor) {
    const int nbs[4]  = {98, 20, 30, 20};
    const int offs[4] = {0, NGW, NGW + NPF, NGW + NPF + NSW};
    const int ns[4]   = {NGW, NPF, NSW, NPF};
    int r = blockIdx.y;
    if ((int)blockIdx.x >= nbs[r]) return;
    const int* c = cnt + offs[r];
    int* rp = rowptr + offs[r];
    int* cu = cursor + offs[r];
    int n = ns[r];

    __shared__ int wsum[8];
    __shared__ int woff[8];
    int t = threadIdx.x;
    int lane = t & 31, warp = t >> 5;
    int base = blockIdx.x * 1024 + t * 4;
    int v[4];
    int tsum = 0;
#pragma unroll
    for (int j = 0; j < 4; j++) {
        int idx = base + j;
        v[j] = (idx < n) ? c[idx] : 0;
        tsum += v[j];
    }
    int incl = tsum;
#pragma unroll
    for (int o = 1; o < 32; o <<= 1) {
        int y = __shfl_up_sync(0xffffffffu, incl, o);
        if (lane >= o) incl += y;
    }
    int excl = incl - tsum;
    if (lane == 31) wsum[warp] = incl;
    __syncthreads();
    if (t == 0) {
        int rr = 0;
        for (int i = 0; i < 8; i++) { woff[i] = rr; rr += wsum[i]; }
    }
    __syncthreads();
    int run = partials[r * 128 + blockIdx.x] + woff[warp] + excl;
#pragma unroll
    for (int j = 0; j < 4; j++) {
        int idx = base + j;
        if (idx < n) { rp[idx] = run; cu[idx] = run; run += v[j]; }
    }
}

__global__ void permute_f(const int* __restrict__ pgs, const int* __restrict__ pgd,
                          const int* __restrict__ gps, const int* __restrict__ gpd,
                          const int* __restrict__ pss, const int* __restrict__ psd,
                          const int* __restrict__ sps, const int* __restrict__ spd,
                          int* __restrict__ cursor, int* __restrict__ perm) {
    int e = blockIdx.x * blockDim.x + threadIdx.x;
    const int *src, *dst;
    int off, poff, le;
    if (e < EPG)                  { src = pgs; dst = pgd; off = 0;               poff = 0;               le = e; }
    else if (e < EPG + EGP)       { src = gps; dst = gpd; off = NGW;             poff = EPG;             le = e - EPG; }
    else if (e < EPG + EGP + EPS) { src = pss; dst = psd; off = NGW + NPF;       poff = EPG + EGP;       le = e - EPG - EGP; }
    else if (e < ETOT)            { src = sps; dst = spd; off = NGW + NPF + NSW; poff = EPG + EGP + EPS; le = e - EPG - EGP - EPS; }
    else return;
    int pos = atomicAdd(&cursor[off + dst[le]], 1);
    perm[poff + pos] = src[le];
}

// ---------------------------------------------------------------------------
// Fused pull aggregation: one warp per destination node across all 4 relations.
// 4-edge batching for memory-level parallelism.
// ---------------------------------------------------------------------------
__global__ __launch_bounds__(256) void aggregate_f(
    const float* __restrict__ xpf, const float* __restrict__ xgw,
    const float* __restrict__ xsw,
    const int* __restrict__ rowptr, const int* __restrict__ perm,
    float* __restrict__ mgw, float* __restrict__ mgp,
    float* __restrict__ msw, float* __restrict__ msp)
{
    int w = (blockIdx.x * blockDim.x + threadIdx.x) >> 5;
    int lane = threadIdx.x & 31;
    if (w >= NTOT) return;

    const float* x;
    float* om;
    int off, poff, N, E, n;
    if (w < NGW)                   { x = xpf; om = mgw; off = 0;               poff = 0;               N = NGW; E = EPG; n = w; }
    else if (w < NGW + NPF)        { x = xgw; om = mgp; off = NGW;             poff = EPG;             N = NPF; E = EGP; n = w - NGW; }
    else if (w < NGW + NPF + NSW)  { x = xpf; om = msw; off = NGW + NPF;       poff = EPG + EGP;       N = NSW; E = EPS; n = w - NGW - NPF; }
    else                           { x = xsw; om = msp; off = NGW + NPF + NSW; poff = EPG + EGP + EPS; N = NPF; E = ESP; n = w - NGW - NPF - NSW; }

    int start = rowptr[off + n];
    int end   = (n + 1 < N) ? rowptr[off + n + 1] : E;
    const int* pp = perm + poff;

    float4 acc = make_float4(0.f, 0.f, 0.f, 0.f);
    for (int e0 = start; e0 < end; e0 += 32) {
        int idx = (e0 + lane < end) ? pp[e0 + lane] : 0;
        int m = min(32, end - e0);
        int j = 0;
        for (; j + 4 <= m; j += 4) {
            int s0 = __shfl_sync(0xffffffffu, idx, j + 0);
            int s1 = __shfl_sync(0xffffffffu, idx, j + 1);
            int s2 = __shfl_sync(0xffffffffu, idx, j + 2);
            int s3 = __shfl_sync(0xffffffffu, idx, j + 3);
            float4 v0 = *reinterpret_cast<const float4*>(x + (size_t)s0 * D + lane * 4);
            float4 v1 = *reinterpret_cast<const float4*>(x + (size_t)s1 * D + lane * 4);
            float4 v2 = *reinterpret_cast<const float4*>(x + (size_t)s2 * D + lane * 4);
            float4 v3 = *reinterpret_cast<const float4*>(x + (size_t)s3 * D + lane * 4);
            acc.x += (v0.x + v1.x) + (v2.x + v3.x);
            acc.y += (v0.y + v1.y) + (v2.y + v3.y);
            acc.z += (v0.z + v1.z) + (v2.z + v3.z);
            acc.w += (v0.w + v1.w) + (v2.w + v3.w);
        }
        for (; j < m; j++) {
            int s = __shfl_sync(0xffffffffu, idx, j);
            float4 v = *reinterpret_cast<const float4*>(x + (size_t)s * D + lane * 4);
            acc.x += v.x; acc.y += v.y; acc.z += v.z; acc.w += v.w;
        }
    }
    float inv = 1.0f / fmaxf((float)(end - start), 1.0f);
    acc.x *= inv; acc.y *= inv; acc.z *= inv; acc.w *= inv;
    *reinterpret_cast<float4*>(om + (size_t)n * D + lane * 4) = acc;
}

// ---------------------------------------------------------------------------
// Fused GEMM, packed f32x2 with PRE-DUPLICATED A operand in SMEM:
// inner loop per k-step is 6 LDS.128 + 32 FFMA2, zero packs.
//   h[row, :] = sum_seg A_seg[row, :] @ W_seg + bias1 (+ bias2)
//   MODE 0: out[row*128 + c] = relu(h)
//   MODE 1: out[row] = relu(h) . whead + bhead
// 128x128 tile per block, 256 threads, 8x8 register tile (8x4 f32x2), KC=16
// ---------------------------------------------------------------------------
template<int NSEG, int MODE>
__global__ __launch_bounds__(256) void gemm_fused(
    const float* __restrict__ A0, const float* __restrict__ A1,
    const float* __restrict__ A2,
    const float* __restrict__ W0, const float* __restrict__ W1,
    const float* __restrict__ W2,
    const float* __restrict__ bias1, const float* __restrict__ bias2,
    const float* __restrict__ whead, const float* __restrict__ bhead,
    float* __restrict__ out, int n_rows)
{
    constexpr int KC  = 16;
    constexpr int LDT = 132;   // Ws row stride (floats): 528B, 16B aligned
    __shared__ unsigned long long As_dup[KC * 128];  // {a,a} pairs, [kk*128 + row]
    __shared__ float Ws[KC][LDT];                    // Ws[kk][col]
    __shared__ float red[128];

    const int t    = threadIdx.x;
    const int row0 = blockIdx.x * 128;
    const int trow = t >> 4;        // 0..15
    const int tcol = t & 15;        // 0..15

    const float* Aseg[3] = {A0, A1, A2};
    const float* Wseg[3] = {W0, W1, W2};

    unsigned long long accp[8][4];
#pragma unroll
    for (int i = 0; i < 8; i++)
#pragma unroll
        for (int j2 = 0; j2 < 4; j2++) accp[i][j2] = 0ull;

    const int nchunks = NSEG * D / KC;
    for (int ch = 0; ch < nchunks; ch++) {
        const int k0   = ch * KC;
        const int seg  = k0 / D;
        const int kin0 = k0 % D;
        const float* A = Aseg[seg];
        const float* W = Wseg[seg];

        // --- A tile: 128 rows x KC, duplicated pairs {a,a}, [kk][row] layout
#pragma unroll
        for (int it = 0; it < 2; it++) {
            int idx  = t + it * 256;     // 0..511
            int row  = idx >> 2;         // 0..127
            int q    = idx & 3;          // 0..3
            int grow = row0 + row;
            float4 v = make_float4(0.f, 0.f, 0.f, 0.f);
            if (grow < n_rows)
                v = *reinterpret_cast<const float4*>(A + (size_t)grow * D + kin0 + q * 4);
            float vv[4] = {v.x, v.y, v.z, v.w};
#pragma unroll
            for (int j = 0; j < 4; j++) {
                unsigned long long p;
                asm("mov.b64 %0, {%1, %1};" : "=l"(p) : "f"(vv[j]));
                As_dup[(q * 4 + j) * 128 + row] = p;
            }
        }
        // --- W tile: KC x 128
#pragma unroll
        for (int it = 0; it < 2; it++) {
            int idx = t + it * 256;      // 0..511
            int kk  = idx >> 5;          // 0..15
            int cq  = idx & 31;          // 0..31
            float4 w = *reinterpret_cast<const float4*>(W + (size_t)(kin0 + kk) * D + cq * 4);
            *reinterpret_cast<float4*>(&Ws[kk][cq * 4]) = w;
        }
        __syncthreads();

#pragma unroll
        for (int kk = 0; kk < KC; kk++) {
            // A: duplicated row pairs, broadcast across half-warp (conflict-free)
            ulonglong2 a01 = *reinterpret_cast<const ulonglong2*>(&As_dup[kk * 128 + trow * 4]);
            ulonglong2 a23 = *reinterpret_cast<const ulonglong2*>(&As_dup[kk * 128 + trow * 4 + 2]);
            ulonglong2 a45 = *reinterpret_cast<const ulonglong2*>(&As_dup[kk * 128 + 64 + trow * 4]);
            ulonglong2 a67 = *reinterpret_cast<const ulonglong2*>(&As_dup[kk * 128 + 64 + trow * 4 + 2]);
            // W: natural column pairs
            ulonglong2 w01 = *reinterpret_cast<const ulonglong2*>(&Ws[kk][tcol * 4]);
            ulonglong2 w23 = *reinterpret_cast<const ulonglong2*>(&Ws[kk][64 + tcol * 4]);
            unsigned long long ap[8] = {a01.x, a01.y, a23.x, a23.y,
                                        a45.x, a45.y, a67.x, a67.y};
            unsigned long long wp[4] = {w01.x, w01.y, w23.x, w23.y};
#pragma unroll
            for (int i = 0; i < 8; i++)
#pragma unroll
                for (int j2 = 0; j2 < 4; j2++)
                    asm("fma.rn.f32x2 %0, %1, %2, %0;"
                        : "+l"(accp[i][j2]) : "l"(ap[i]), "l"(wp[j2]));
        }
        __syncthreads();
    }

    float acc[8][8];
#pragma unroll
    for (int i = 0; i < 8; i++)
#pragma unroll
        for (int j2 = 0; j2 < 4; j2++)
            asm("mov.b64 {%0, %1}, %2;"
                : "=f"(acc[i][2 * j2]), "=f"(acc[i][2 * j2 + 1]) : "l"(accp[i][j2]));

    int cidx[8], ridx[8];
#pragma unroll
    for (int j = 0; j < 8; j++)
        cidx[j] = (j < 4) ? (tcol * 4 + j) : (64 + tcol * 4 + (j - 4));
#pragma unroll
    for (int i = 0; i < 8; i++)
        ridx[i] = (i < 4) ? (trow * 4 + i) : (64 + trow * 4 + (i - 4));

    float b[8];
#pragma unroll
    for (int j = 0; j < 8; j++)
        b[j] = bias1[cidx[j]] + (bias2 ? bias2[cidx[j]] : 0.f);

    if (MODE == 0) {
#pragma unroll
        for (int i = 0; i < 8; i++) {
            int grow = row0 + ridx[i];
            if (grow < n_rows) {
#pragma unroll
                for (int j = 0; j < 8; j++)
                    out[(size_t)grow * D + cidx[j]] = fmaxf(acc[i][j] + b[j], 0.f);
            }
        }
    } else {
        float wh[8];
#pragma unroll
        for (int j = 0; j < 8; j++) wh[j] = whead[cidx[j]];
        if (t < 128) red[t] = 0.f;
        __syncthreads();
#pragma unroll
        for (int i = 0; i < 8; i++) {
            float partial = 0.f;
#pragma unroll
            for (int j = 0; j < 8; j++)
                partial += fmaxf(acc[i][j] + b[j], 0.f) * wh[j];
            atomicAdd(&red[ridx[i]], partial);
        }
        __syncthreads();
        if (t < 128) {
            int grow = row0 + t;
            if (grow < n_rows) out[grow] = red[t] + bhead[0];
        }
    }
}

// ---------------------------------------------------------------------------
// Launch
// ---------------------------------------------------------------------------
extern "C" void kernel_launch(void* const* d_in, const int* in_sizes, int n_in,
                              void* d_out, int out_size)
{
    const float* x_pfas = (const float*)d_in[0];
    const float* x_gw   = (const float*)d_in[1];
    const float* x_sw   = (const float*)d_in[2];
    const int* ei_pg_src = (const int*)d_in[3];
    const int* ei_pg_dst = (const int*)d_in[4];
    const int* ei_gp_src = (const int*)d_in[5];
    const int* ei_gp_dst = (const int*)d_in[6];
    const int* ei_ps_src = (const int*)d_in[7];
    const int* ei_ps_dst = (const int*)d_in[8];
    const int* ei_sp_src = (const int*)d_in[9];
    const int* ei_sp_dst = (const int*)d_in[10];
    const float* Wl_pg = (const float*)d_in[11];
    const float* bl_pg = (const float*)d_in[12];
    const float* Wr_pg = (const float*)d_in[13];
    const float* Wl_gp = (const float*)d_in[14];
    const float* bl_gp = (const float*)d_in[15];
    const float* Wr_gp = (const float*)d_in[16];
    const float* Wl_ps = (const float*)d_in[17];
    const float* bl_ps = (const float*)d_in[18];
    const float* Wr_ps = (const float*)d_in[19];
    const float* Wl_sp = (const float*)d_in[20];
    const float* bl_sp = (const float*)d_in[21];
    const float* Wr_sp = (const float*)d_in[22];
    const float* W_gw  = (const float*)d_in[23];
    const float* b_gw  = (const float*)d_in[24];
    const float* W_sw  = (const float*)d_in[25];
    const float* b_sw  = (const float*)d_in[26];

    float* out = (float*)d_out;
    float* out_hpf = out;                       // [20000, 128]
    float* out_gw  = out + (size_t)NPF * D;     // [100000]
    float* out_sw  = out_gw + NGW;              // [30000]

    static float *mean_gw = nullptr, *mean_sw = nullptr, *mean_gp = nullptr, *mean_sp = nullptr;
    static float *wr_comb = nullptr;
    static int *cnt = nullptr, *rowptr = nullptr, *cursor = nullptr, *perm = nullptr, *partials = nullptr;
    if (!mean_gw) {
        cudaGetSymbolAddress((void**)&mean_gw, g_mean_gw);
        cudaGetSymbolAddress((void**)&mean_sw, g_mean_sw);
        cudaGetSymbolAddress((void**)&mean_gp, g_mean_gp);
        cudaGetSymbolAddress((void**)&mean_sp, g_mean_sp);
        cudaGetSymbolAddress((void**)&wr_comb, g_wr_comb);
        cudaGetSymbolAddress((void**)&cnt, g_cnt);
        cudaGetSymbolAddress((void**)&rowptr, g_rowptr);
        cudaGetSymbolAddress((void**)&cursor, g_cursor);
        cudaGetSymbolAddress((void**)&perm, g_perm);
        cudaGetSymbolAddress((void**)&partials, g_partials);
    }

    // ---- 1) zero counters + fold Wr weights ----
    zero_int_kernel<<<(NTOT / 4 + 255) / 256, 256>>>(cnt, NTOT / 4);
    addw_kernel<<<(D * D + 255) / 256, 256>>>(Wr_gp, Wr_sp, wr_comb);

    // ---- 2) fused CSR build ----
    hist_f<<<(ETOT + 255) / 256, 256>>>(ei_pg_dst, ei_gp_dst, ei_ps_dst, ei_sp_dst, cnt);
    {
        dim3 g(98, 4);
        scan_reduce_f<<<g, 256>>>(cnt, partials);
        scan_partials_f<<<1, 4>>>(partials);
        scan_write_f<<<g, 256>>>(cnt, partials, rowptr, cursor);
    }
    permute_f<<<(ETOT + 255) / 256, 256>>>(
        ei_pg_src, ei_pg_dst, ei_gp_src, ei_gp_dst,
        ei_ps_src, ei_ps_dst, ei_sp_src, ei_sp_dst,
        cursor, perm);

    // ---- 3) fused pull aggregation (all 4 relations) ----
    aggregate_f<<<(NTOT + 7) / 8, 256>>>(
        x_pfas, x_gw, x_sw, rowptr, perm,
        mean_gw, mean_gp, mean_sw, mean_sp);

    // ---- 4) fused GEMMs ----
    // pfas: relu(mean_gp@Wl_gp + mean_sp@Wl_sp + x_pfas@(Wr_gp+Wr_sp) + biases)
    gemm_fused<3, 0><<<(NPF + 127) / 128, 256>>>(
        mean_gp, mean_sp, x_pfas,
        Wl_gp, Wl_sp, wr_comb,
        bl_gp, bl_sp, nullptr, nullptr,
        out_hpf, NPF);

    // gw head: relu(mean_gw@Wl_pg + x_gw@Wr_pg + bl_pg) @ W_gw + b_gw
    gemm_fused<2, 1><<<(NGW + 127) / 128, 256>>>(
        mean_gw, x_gw, nullptr,
        Wl_pg, Wr_pg, nullptr,
        bl_pg, nullptr, W_gw, b_gw,
        out_gw, NGW);

    // sw head: relu(mean_sw@Wl_ps + x_sw@Wr_ps + bl_ps) @ W_sw + b_sw
    gemm_fused<2, 1><<<(NSW + 127) / 128, 256>>>(
        mean_sw, x_sw, nullptr,
        Wl_ps, Wr_ps, nullptr,
        bl_ps, nullptr, W_sw, b_sw,
        out_sw, NSW);

    (void)n_in; (void)out_size; (void)in_sizes;
}